// round 7
// baseline (speedup 1.0000x reference)
#include <cuda_runtime.h>
#include <cuda_bf16.h>
#include <math.h>
#include <stdint.h>

#define B_ 256

// ---------------- device scratch ----------------
__device__ float g_Weff[25 * 220];
__device__ float g_beff[25];
__device__ uint32_t g_y1p[B_ * 25 * 330];            // packed bf16 h | l<<16
__device__ uint32_t g_y2p[B_ * 50 * 107];            // packed bf16 h | l<<16
__device__ float g_y3[B_ * 100 * 32];
__device__ float g_feat[B_ * 1400];
// w3 bf16 split, chunk-image layout: [4 chunks][128 rows][136 k]
__device__ __align__(16) uint16_t g_w3h[4 * 128 * 136];
__device__ __align__(16) uint16_t g_w3l[4 * 128 * 136];
// w2 bf16 split, chunk-image layout: [2 chunks][64 rows][136 k]
__device__ __align__(16) uint16_t g_w2h[2 * 64 * 136];
__device__ __align__(16) uint16_t g_w2l[2 * 64 * 136];

__device__ __forceinline__ float elu1(float x) { return x > 0.f ? x : expm1f(x); }

__device__ __forceinline__ uint32_t smem_u32(const void* p) {
    uint32_t a;
    asm("{ .reg .u64 t; cvta.to.shared.u64 t, %1; cvt.u32.u64 %0, t; }" : "=r"(a) : "l"(p));
    return a;
}
__device__ __forceinline__ void ldsm4(uint32_t* r, uint32_t addr) {
    asm volatile("ldmatrix.sync.aligned.m8n8.x4.shared.b16 {%0,%1,%2,%3}, [%4];"
                 : "=r"(r[0]), "=r"(r[1]), "=r"(r[2]), "=r"(r[3]) : "r"(addr));
}
__device__ __forceinline__ void ldsm4t(uint32_t* r, uint32_t addr) {
    asm volatile("ldmatrix.sync.aligned.m8n8.x4.trans.shared.b16 {%0,%1,%2,%3}, [%4];"
                 : "=r"(r[0]), "=r"(r[1]), "=r"(r[2]), "=r"(r[3]) : "r"(addr));
}
__device__ __forceinline__ void mma16816(float* d, const uint32_t* a, const uint32_t* b) {
    asm volatile("mma.sync.aligned.m16n8k16.row.col.f32.bf16.bf16.f32 "
                 "{%0,%1,%2,%3}, {%4,%5,%6,%7}, {%8,%9}, {%0,%1,%2,%3};"
                 : "+f"(d[0]), "+f"(d[1]), "+f"(d[2]), "+f"(d[3])
                 : "r"(a[0]), "r"(a[1]), "r"(a[2]), "r"(a[3]), "r"(b[0]), "r"(b[1]));
}
__device__ __forceinline__ uint32_t pack_bf16_split(float v) {
    __nv_bfloat16 h = __float2bfloat16(v);
    float hf = __bfloat162float(h);
    __nv_bfloat16 l = __float2bfloat16(v - hf);
    uint16_t hb = reinterpret_cast<uint16_t&>(h);
    uint16_t lb = reinterpret_cast<uint16_t&>(l);
    return (uint32_t)hb | ((uint32_t)lb << 16);
}

// ---------------- kernel 0: fold conv_time into conv_spat ----------------
__global__ void precompute_k(const float* __restrict__ w_time, const float* __restrict__ b_time,
                             const float* __restrict__ w_spat, const float* __restrict__ b_spat)
{
    for (int idx = threadIdx.x; idx < 25 * 220; idx += blockDim.x) {
        int p = idx / 220, rem = idx % 220, c = rem / 10, k = rem % 10;
        float s = 0.f;
        #pragma unroll
        for (int o = 0; o < 25; o++)
            s = fmaf(w_spat[p * 550 + o * 22 + c], w_time[o * 10 + k], s);
        g_Weff[idx] = s;
    }
    if (threadIdx.x < 25) {
        int p = threadIdx.x;
        float s = b_spat[p];
        for (int o = 0; o < 25; o++) {
            float w = 0.f;
            for (int c = 0; c < 22; c++) w += w_spat[p * 550 + o * 22 + c];
            s = fmaf(b_time[o], w, s);
        }
        g_beff[p] = s;
    }
}

// ---------------- kernel 0b: w3 bf16 split into chunk-image layout ----------------
__global__ void precompute2_k(const float* __restrict__ w3)   // [100][500]
{
    int idx = blockIdx.x * 256 + threadIdx.x;
    if (idx >= 4 * 128 * 136) return;
    int ch = idx / 17408, r = idx % 17408, row = r / 136, kloc = r % 136;
    int gk = ch * 128 + kloc;
    float v = (kloc < 128 && row < 100 && gk < 500) ? w3[row * 500 + gk] : 0.f;
    uint32_t p = pack_bf16_split(v);
    g_w3h[idx] = (uint16_t)(p & 0xffff);
    g_w3l[idx] = (uint16_t)(p >> 16);
}

// ---------------- kernel 0c: w2 bf16 split into chunk-image layout ----------------
__global__ void precompute3_k(const float* __restrict__ w2)   // [50][250]
{
    int idx = blockIdx.x * 256 + threadIdx.x;
    if (idx >= 2 * 64 * 136) return;
    int ch = idx / 8704, r = idx % 8704, row = r / 136, kloc = r % 136;
    int gk = ch * 128 + kloc;
    float v = (kloc < 128 && row < 50 && gk < 250) ? w2[row * 250 + gk] : 0.f;
    uint32_t p = pack_bf16_split(v);
    g_w2h[idx] = (uint16_t)(p & 0xffff);
    g_w2l[idx] = (uint16_t)(p >> 16);
}

// ---------------- scalar conv body ----------------
template<int P, int C, int XS, int WS>
__device__ __forceinline__ void conv_acc(const float* __restrict__ xs,
                                         const float* __restrict__ ws,
                                         float* __restrict__ acc)
{
    #pragma unroll
    for (int i = 0; i < P * 3; i++) acc[i] = 0.f;
    #pragma unroll 1
    for (int c = 0; c < C; c++) {
        float xr[12];
        #pragma unroll
        for (int i = 0; i < 12; i++) xr[i] = xs[c * XS + i];
        #pragma unroll
        for (int p = 0; p < P; p++) {
            const float* wp = ws + p * WS + c * 12;
            float4 w0 = *reinterpret_cast<const float4*>(wp);
            float4 w1 = *reinterpret_cast<const float4*>(wp + 4);
            float2 w2 = *reinterpret_cast<const float2*>(wp + 8);
            float wk[10] = {w0.x, w0.y, w0.z, w0.w, w1.x, w1.y, w1.z, w1.w, w2.x, w2.y};
            #pragma unroll
            for (int k = 0; k < 10; k++) {
                acc[p * 3 + 0] = fmaf(wk[k], xr[k + 0], acc[p * 3 + 0]);
                acc[p * 3 + 1] = fmaf(wk[k], xr[k + 1], acc[p * 3 + 1]);
                acc[p * 3 + 2] = fmaf(wk[k], xr[k + 2], acc[p * 3 + 2]);
            }
        }
    }
}

// ---------------- stage 1: x[256,22,1000] -> y1p[256,25,330] (packed) ----------------
__global__ __launch_bounds__(352, 2) void stage1_k(const float* __restrict__ x)
{
    extern __shared__ float sm[];
    float* xs = sm;                // [22][504]
    float* ws = sm + 22 * 504;     // [25][264]
    __shared__ float bs[25];
    const int b = blockIdx.x, half = blockIdx.y;
    const int xoff = half * 495;
    const float* xb = x + b * 22000;
    for (int i = threadIdx.x; i < 22 * 504; i += 352) {
        int c = i / 504, t = i - c * 504;
        xs[i] = xb[c * 1000 + xoff + t];
    }
    for (int i = threadIdx.x; i < 5500; i += 352) {
        int p = i / 220, r = i - p * 220;
        int c = r / 10, k = r - c * 10;
        ws[p * 264 + c * 12 + k] = g_Weff[i];
    }
    if (threadIdx.x < 25) bs[threadIdx.x] = g_beff[threadIdx.x];
    __syncthreads();

    const int tpL = threadIdx.x % 176;
    const int pg  = threadIdx.x / 176;
    if (tpL >= 165) return;
    const float* xp = xs + 3 * tpL;
    const int tp = half * 165 + tpL;

    if (pg == 0) {
        float acc[39];
        conv_acc<13, 22, 504, 264>(xp, ws, acc);
        #pragma unroll
        for (int p = 0; p < 13; p++) {
            float m = fmaxf(acc[p * 3], fmaxf(acc[p * 3 + 1], acc[p * 3 + 2])) + bs[p];
            g_y1p[b * 8250 + p * 330 + tp] = pack_bf16_split(elu1(m));
        }
    } else {
        float acc[36];
        conv_acc<12, 22, 504, 264>(xp, ws + 13 * 264, acc);
        #pragma unroll
        for (int p = 0; p < 12; p++) {
            float m = fmaxf(acc[p * 3], fmaxf(acc[p * 3 + 1], acc[p * 3 + 2])) + bs[13 + p];
            g_y1p[b * 8250 + (13 + p) * 330 + tp] = pack_bf16_split(elu1(m));
        }
    }
}

// ---------------- stage 2 (TENSOR): y1p -> y2p ----------------
// grid (256 samples, 2 N-tiles). D[64][192] = A(w2)[64][256] x B(im2col y1)[192][256]^T
#define S2_KP 136
#define S2_NP 200
#define S2_AH 0
#define S2_AL 17408
#define S2_BH 34816
#define S2_BL 86016
#define S2_SMEM 137216

__global__ __launch_bounds__(256, 1) void stage2_k(const float* __restrict__ b2)
{
    extern __shared__ char smc[];
    const uint32_t sb = smem_u32(smc);
    const int tid = threadIdx.x, wid = tid >> 5, lane = tid & 31;
    const int b = blockIdx.x, ntile = blockIdx.y;
    const int n0 = ntile * 168;

    float d[12][4];
    #pragma unroll
    for (int i = 0; i < 12; i++)
        #pragma unroll
        for (int j = 0; j < 4; j++) d[i][j] = 0.f;

    const int mw = wid & 3, nw = wid >> 2;
    const uint32_t aOff = ((mw * 16 + ((lane >> 3) & 1) * 8 + (lane & 7)) * S2_KP + (lane >> 4) * 8) * 2;
    const uint32_t bOff = ((((lane >> 3) & 1) * 8 + (lane & 7)) * S2_NP + (lane >> 4) * 8 + nw * 96) * 2;
    const uint32_t aH = sb + S2_AH + aOff, aL = sb + S2_AL + aOff;
    const uint32_t bHb = sb + S2_BH + bOff, bLb = sb + S2_BL + bOff;

    const int kloc = tid >> 1, seg = tid & 1;
    uint16_t* bhRow = reinterpret_cast<uint16_t*>(smc + S2_BH) + kloc * S2_NP + seg * 96;
    uint16_t* blRow = reinterpret_cast<uint16_t*>(smc + S2_BL) + kloc * S2_NP + seg * 96;

    for (int ch = 0; ch < 2; ch++) {
        __syncthreads();
        // A copy: chunk image (8704 uint16 per split = 1088 float4)
        {
            const float4* srcH = reinterpret_cast<const float4*>(g_w2h + ch * 8704);
            const float4* srcL = reinterpret_cast<const float4*>(g_w2l + ch * 8704);
            float4* dstH = reinterpret_cast<float4*>(smc + S2_AH);
            float4* dstL = reinterpret_cast<float4*>(smc + S2_AL);
            #pragma unroll 1
            for (int i = tid; i < 1088; i += 256) { dstH[i] = srcH[i]; dstL[i] = srcL[i]; }
        }
        // B gather from packed y1
        {
            const int gk = ch * 128 + kloc;
            if (gk < 250) {
                const int c = gk / 10, kk = gk - c * 10;
                const uint32_t* src = g_y1p + b * 8250 + c * 330 + n0 + kk;
                const int jmax = 330 - n0 - kk;   // j + seg*96 < jmax stays in this row
                #pragma unroll 8
                for (int j = 0; j < 96; j++) {
                    int jj = seg * 96 + j;
                    uint32_t p = (jj < jmax) ? __ldg(&src[jj]) : 0u;
                    bhRow[j] = (uint16_t)(p & 0xffff);
                    blRow[j] = (uint16_t)(p >> 16);
                }
            } else {
                #pragma unroll 8
                for (int j = 0; j < 96; j++) { bhRow[j] = 0; blRow[j] = 0; }
            }
        }
        __syncthreads();

        #pragma unroll
        for (int t = 0; t < 8; t++) {
            uint32_t ah[4], al[4];
            ldsm4(ah, aH + t * 32);
            ldsm4(al, aL + t * 32);
            const uint32_t bt = (uint32_t)t * (16 * S2_NP * 2);
            #pragma unroll
            for (int q = 0; q < 6; q++) {
                uint32_t bh[4], bl[4];
                ldsm4t(bh, bHb + bt + q * 32);
                ldsm4t(bl, bLb + bt + q * 32);
                mma16816(d[2 * q],     ah, bh);
                mma16816(d[2 * q],     al, bh);
                mma16816(d[2 * q],     ah, bl);
                mma16816(d[2 * q + 1], ah, bh + 2);
                mma16816(d[2 * q + 1], al, bh + 2);
                mma16816(d[2 * q + 1], ah, bl + 2);
            }
        }
    }

    // epilogue: D -> smem f32 [64][200], pool + ELU + pack
    __syncthreads();
    float* Dsm = reinterpret_cast<float*>(smc);
    {
        const int r0 = mw * 16 + (lane >> 2);
        const int cb = (lane & 3) * 2;
        #pragma unroll
        for (int q = 0; q < 6; q++) {
            int n = nw * 96 + q * 16 + cb;
            Dsm[r0 * 200 + n]           = d[2 * q][0];
            Dsm[r0 * 200 + n + 1]       = d[2 * q][1];
            Dsm[(r0 + 8) * 200 + n]     = d[2 * q][2];
            Dsm[(r0 + 8) * 200 + n + 1] = d[2 * q][3];
            Dsm[r0 * 200 + n + 8]       = d[2 * q + 1][0];
            Dsm[r0 * 200 + n + 9]       = d[2 * q + 1][1];
            Dsm[(r0 + 8) * 200 + n + 8] = d[2 * q + 1][2];
            Dsm[(r0 + 8) * 200 + n + 9] = d[2 * q + 1][3];
        }
    }
    __syncthreads();
    const int cnt = ntile ? 50 * 51 : 50 * 56;
    for (int i = tid; i < cnt; i += 256) {
        int o, p;
        if (ntile == 0) { o = i / 56; p = i - o * 56; }
        else            { o = i / 51; p = 56 + (i - o * 51); }
        int nl = 3 * p - n0;
        float v = fmaxf(Dsm[o * 200 + nl], fmaxf(Dsm[o * 200 + nl + 1], Dsm[o * 200 + nl + 2]))
                  + __ldg(&b2[o]);
        g_y2p[b * 5350 + o * 107 + p] = pack_bf16_split(elu1(v));
    }
}

// ---------------- stage 3 (TENSOR): y2p -> y3 ----------------
#define S3_KP 136
#define S3_NP 200
#define S3_AH 0
#define S3_AL 34816
#define S3_BH 69632
#define S3_BL 120832
#define S3_SMEM 172032

__global__ __launch_bounds__(256, 1) void stage3_k(const float* __restrict__ b3)
{
    extern __shared__ char smc[];
    const uint32_t sb = smem_u32(smc);
    const int tid = threadIdx.x, wid = tid >> 5, lane = tid & 31;
    const int s0 = blockIdx.x * 2;

    float d[24][4];
    #pragma unroll
    for (int i = 0; i < 24; i++)
        #pragma unroll
        for (int j = 0; j < 4; j++) d[i][j] = 0.f;

    const uint32_t aOff = ((wid * 16 + ((lane >> 3) & 1) * 8 + (lane & 7)) * S3_KP + (lane >> 4) * 8) * 2;
    const uint32_t bOff = ((((lane >> 3) & 1) * 8 + (lane & 7)) * S3_NP + (lane >> 4) * 8) * 2;
    const uint32_t aH = sb + S3_AH + aOff, aL = sb + S3_AL + aOff;
    const uint32_t bHb = sb + S3_BH + bOff, bLb = sb + S3_BL + bOff;

    const int kloc = tid >> 1, seg = tid & 1;
    uint16_t* bhRow = reinterpret_cast<uint16_t*>(smc + S3_BH) + kloc * S3_NP + seg * 96;
    uint16_t* blRow = reinterpret_cast<uint16_t*>(smc + S3_BL) + kloc * S3_NP + seg * 96;

    for (int ch = 0; ch < 4; ch++) {
        __syncthreads();
        {
            const float4* srcH = reinterpret_cast<const float4*>(g_w3h + ch * 17408);
            const float4* srcL = reinterpret_cast<const float4*>(g_w3l + ch * 17408);
            float4* dstH = reinterpret_cast<float4*>(smc + S3_AH);
            float4* dstL = reinterpret_cast<float4*>(smc + S3_AL);
            #pragma unroll 1
            for (int i = tid; i < 2176; i += 256) { dstH[i] = srcH[i]; dstL[i] = srcL[i]; }
        }
        {
            const int gk = ch * 128 + kloc;
            if (gk < 500) {
                const int c = gk / 10, kk = gk - c * 10;
                const uint32_t* src = g_y2p + (s0 + seg) * 5350 + c * 107 + kk;
                #pragma unroll 8
                for (int j = 0; j < 96; j++) {
                    uint32_t p = __ldg(&src[j]);
                    bhRow[j] = (uint16_t)(p & 0xffff);
                    blRow[j] = (uint16_t)(p >> 16);
                }
            } else {
                #pragma unroll 8
                for (int j = 0; j < 96; j++) { bhRow[j] = 0; blRow[j] = 0; }
            }
        }
        __syncthreads();

        #pragma unroll
        for (int t = 0; t < 8; t++) {
            uint32_t ah[4], al[4];
            ldsm4(ah, aH + t * 32);
            ldsm4(al, aL + t * 32);
            const uint32_t bt = (uint32_t)t * (16 * S3_NP * 2);
            #pragma unroll
            for (int q = 0; q < 12; q++) {
                uint32_t bh[4], bl[4];
                ldsm4t(bh, bHb + bt + q * 32);
                ldsm4t(bl, bLb + bt + q * 32);
                mma16816(d[2 * q],     ah, bh);
                mma16816(d[2 * q],     al, bh);
                mma16816(d[2 * q],     ah, bl);
                mma16816(d[2 * q + 1], ah, bh + 2);
                mma16816(d[2 * q + 1], al, bh + 2);
                mma16816(d[2 * q + 1], ah, bl + 2);
            }
        }
    }

    __syncthreads();
    float* Dsm = reinterpret_cast<float*>(smc);
    {
        const int r0 = wid * 16 + (lane >> 2);
        const int cb = (lane & 3) * 2;
        #pragma unroll
        for (int nt = 0; nt < 24; nt++) {
            int n = nt * 8 + cb;
            Dsm[r0 * 200 + n]           = d[nt][0];
            Dsm[r0 * 200 + n + 1]       = d[nt][1];
            Dsm[(r0 + 8) * 200 + n]     = d[nt][2];
            Dsm[(r0 + 8) * 200 + n + 1] = d[nt][3];
        }
    }
    __syncthreads();
    for (int i = tid; i < 6400; i += 256) {
        int o = i >> 6, r = i & 63, s = r >> 5, t = r & 31;
        int n = s * 96 + t * 3;
        float v = fmaxf(Dsm[o * 200 + n], fmaxf(Dsm[o * 200 + n + 1], Dsm[o * 200 + n + 2]))
                  + __ldg(&b3[o]);
        g_y3[(s0 + s) * 3200 + o * 32 + t] = elu1(v);
    }
}

// ---------------- stage 4: y3 -> feat[256,1400] ----------------
__global__ __launch_bounds__(224, 3) void stage4_k(const float* __restrict__ w4,
                                                   const float* __restrict__ b4)
{
    extern __shared__ float sm[];
    float* xs = sm;             // [100][32]
    float* wc = sm + 3200;      // [50][201]
    const int b = blockIdx.x;
    const int o = threadIdx.x;
    for (int i = threadIdx.x; i < 3200; i += 224) xs[i] = g_y3[b * 3200 + i];

    float acc[21];
    #pragma unroll
    for (int i = 0; i < 21; i++) acc[i] = 0.f;

    for (int c0 = 0; c0 < 100; c0 += 5) {
        __syncthreads();
        const float2* wg = reinterpret_cast<const float2*>(w4 + c0 * 10);
        for (int i = threadIdx.x; i < 5000; i += 224) {
            int oo = i / 25, r2 = i - oo * 25;
            float2 v = __ldg(&wg[oo * 500 + r2]);
            wc[(2 * r2) * 201 + oo]     = v.x;
            wc[(2 * r2 + 1) * 201 + oo] = v.y;
        }
        __syncthreads();
        if (o < 200) {
            #pragma unroll
            for (int c = 0; c < 5; c++) {
                float xr[32];
                const float4* xp = reinterpret_cast<const float4*>(xs + (c0 + c) * 32);
                #pragma unroll
                for (int q = 0; q < 8; q++) {
                    float4 v = xp[q];
                    xr[q * 4 + 0] = v.x; xr[q * 4 + 1] = v.y;
                    xr[q * 4 + 2] = v.z; xr[q * 4 + 3] = v.w;
                }
                #pragma unroll
                for (int k = 0; k < 10; k++) {
                    float wv = wc[(c * 10 + k) * 201 + o];
                    #pragma unroll
                    for (int j = 0; j < 21; j++)
                        acc[j] = fmaf(wv, xr[j + k], acc[j]);
                }
            }
        }
    }

    if (o < 200) {
        float bo = __ldg(&b4[o]);
        #pragma unroll
        for (int t = 0; t < 7; t++) {
            float m = fmaxf(acc[3 * t], fmaxf(acc[3 * t + 1], acc[3 * t + 2])) + bo;
            g_feat[b * 1400 + o * 7 + t] = elu1(m);
        }
    }
}

// ---------------- head ----------------
__global__ void head_k(const int* __restrict__ sid, const float* __restrict__ hW,
                       const float* __restrict__ hB, float* __restrict__ out)
{
    const int b = blockIdx.x;
    const int s = sid[b];
    const float* f = g_feat + b * 1400;
    const float* W = hW + s * (4 * 1400);
    float acc[4] = {0.f, 0.f, 0.f, 0.f};
    for (int i = threadIdx.x; i < 1400; i += blockDim.x) {
        float fv = f[i];
        #pragma unroll
        for (int o = 0; o < 4; o++) acc[o] = fmaf(fv, __ldg(&W[o * 1400 + i]), acc[o]);
    }
    #pragma unroll
    for (int off = 16; off > 0; off >>= 1) {
        #pragma unroll
        for (int o = 0; o < 4; o++) acc[o] += __shfl_down_sync(0xFFFFFFFFu, acc[o], off);
    }
    __shared__ float red[4][4];
    const int w = threadIdx.x >> 5, l = threadIdx.x & 31;
    if (l == 0) {
        #pragma unroll
        for (int o = 0; o < 4; o++) red[o][w] = acc[o];
    }
    __syncthreads();
    if (threadIdx.x < 4) {
        int o = threadIdx.x;
        out[b * 4 + o] = red[o][0] + red[o][1] + red[o][2] + red[o][3] + __ldg(&hB[s * 4 + o]);
    }
}

// ---------------- launch ----------------
extern "C" void kernel_launch(void* const* d_in, const int* in_sizes, int n_in,
                              void* d_out, int out_size)
{
    const float* x      = (const float*)d_in[0];
    const int*   sid    = (const int*)  d_in[1];
    const float* w_time = (const float*)d_in[2];
    const float* b_time = (const float*)d_in[3];
    const float* w_spat = (const float*)d_in[4];
    const float* b_spat = (const float*)d_in[5];
    const float* w2     = (const float*)d_in[6];
    const float* b2     = (const float*)d_in[7];
    const float* w3     = (const float*)d_in[8];
    const float* b3     = (const float*)d_in[9];
    const float* w4     = (const float*)d_in[10];
    const float* b4     = (const float*)d_in[11];
    const float* hW     = (const float*)d_in[12];
    const float* hB     = (const float*)d_in[13];
    float* out = (float*)d_out;

    const int smem1 = (22 * 504 + 25 * 264) * 4;     // 70,752
    const int smem2 = S2_SMEM;                       // 137,216
    const int smem3 = S3_SMEM;                       // 172,032
    const int smem4 = (3200 + 50 * 201 + 3) * 4;     // 53,012
    cudaFuncSetAttribute(stage1_k, cudaFuncAttributeMaxDynamicSharedMemorySize, smem1);
    cudaFuncSetAttribute(stage2_k, cudaFuncAttributeMaxDynamicSharedMemorySize, smem2);
    cudaFuncSetAttribute(stage3_k, cudaFuncAttributeMaxDynamicSharedMemorySize, smem3);
    cudaFuncSetAttribute(stage4_k, cudaFuncAttributeMaxDynamicSharedMemorySize, smem4);

    precompute_k<<<1, 256>>>(w_time, b_time, w_spat, b_spat);
    precompute2_k<<<(4 * 128 * 136 + 255) / 256, 256>>>(w3);
    precompute3_k<<<(2 * 64 * 136 + 255) / 256, 256>>>(w2);
    stage1_k<<<dim3(B_, 2), 352, smem1>>>(x);
    stage2_k<<<dim3(B_, 2), 256, smem2>>>(b2);
    stage3_k<<<128, 256, smem3>>>(b3);
    stage4_k<<<B_, 224, smem4>>>(w4, b4);
    head_k<<<B_, 128>>>(sid, hW, hB, out);
}